// round 7
// baseline (speedup 1.0000x reference)
#include <cuda_runtime.h>
#include <cstdint>

#define NND 50000
#define NED 400000

// ---------------- device scratch (no allocations allowed) ----------------
__device__ int g_is64;
__device__ int g_src[NED];
__device__ int g_dst[NED];
__device__ int g_deg[NND];
__device__ int g_rowptr[NND + 1];
__device__ int g_cursor[NND];
__device__ int g_esort[NED];

__device__ float g_bufA[(size_t)NND * 512];   // linear-transform output h
__device__ float g_bufB[(size_t)NND * 512];   // aggregated layer output
__device__ float g_bufC[(size_t)NND * 16];    // final-layer h

__device__ float g_als[NND * 8];
__device__ float g_ald[NND * 8];
__device__ unsigned int g_menc[NND * 8];
__device__ float g_mf[NND * 8];
__device__ float g_denom[NND * 8];
__device__ float g_exself[NND * 8];
__device__ float g_exbuf[(size_t)NED * 8];

__device__ __forceinline__ float* pickbuf(int s) {
    return s == 0 ? g_bufA : (s == 1 ? g_bufB : g_bufC);
}
// order-preserving float <-> uint encoding for atomicMax
__device__ __forceinline__ unsigned fenc(float f) {
    unsigned u = __float_as_uint(f);
    return (u & 0x80000000u) ? ~u : (u | 0x80000000u);
}
__device__ __forceinline__ float fdec(unsigned u) {
    return __uint_as_float((u & 0x80000000u) ? (u ^ 0x80000000u) : ~u);
}
__device__ __forceinline__ float lrelu(float v) { return v > 0.f ? v : 0.2f * v; }

// ---------------- edge index dtype detect + convert ----------------
__global__ void detect_kernel(const void* ei) {
    if (threadIdx.x == 0 && blockIdx.x == 0) {
        const int* p = (const int*)ei;
        int is64 = 1;
        for (int i = 0; i < 128; i++) {
            if (p[2 * i + 1] != 0) { is64 = 0; break; }
        }
        g_is64 = is64;
    }
}

__global__ void convert_kernel(const void* ei) {
    int e = blockIdx.x * blockDim.x + threadIdx.x;
    if (e >= NED) return;
    if (g_is64) {
        const long long* p = (const long long*)ei;
        g_src[e] = (int)p[e];
        g_dst[e] = (int)p[NED + e];
    } else {
        const int* p = (const int*)ei;
        g_src[e] = p[e];
        g_dst[e] = p[NED + e];
    }
}

// ---------------- CSR build (by destination) ----------------
__global__ void zero_deg_kernel() {
    int i = blockIdx.x * blockDim.x + threadIdx.x;
    if (i < NND) g_deg[i] = 0;
}
__global__ void count_kernel() {
    int e = blockIdx.x * blockDim.x + threadIdx.x;
    if (e >= NED) return;
    atomicAdd(&g_deg[g_dst[e]], 1);
}
__global__ void scan_kernel() {  // single block, 1024 threads
    __shared__ int sh[1024];
    __shared__ int s_carry;
    int tid = threadIdx.x;
    if (tid == 0) s_carry = 0;
    __syncthreads();
    for (int base = 0; base < NND; base += 1024) {
        int i = base + tid;
        int v = (i < NND) ? g_deg[i] : 0;
        sh[tid] = v;
        __syncthreads();
        for (int off = 1; off < 1024; off <<= 1) {
            int t = (tid >= off) ? sh[tid - off] : 0;
            __syncthreads();
            sh[tid] += t;
            __syncthreads();
        }
        int excl = s_carry + sh[tid] - v;
        if (i < NND) { g_rowptr[i] = excl; g_cursor[i] = excl; }
        __syncthreads();
        if (tid == 0) s_carry += sh[1023];
        __syncthreads();
    }
    if (tid == 0) g_rowptr[NND] = s_carry;
}
__global__ void scatter_kernel() {
    int e = blockIdx.x * blockDim.x + threadIdx.x;
    if (e >= NED) return;
    int pos = atomicAdd(&g_cursor[g_dst[e]], 1);
    g_esort[pos] = e;
}

// ---------------- SGEMM 128x128x8, fp32, 256 threads ----------------
__global__ __launch_bounds__(256) void sgemm128(
    const float* __restrict__ Aext, int aSel,
    const float* __restrict__ B, int cSel,
    int M, int K, int Nn)
{
    const float* A = (aSel < 0) ? Aext : pickbuf(aSel);
    float* C = pickbuf(cSel);

    __shared__ __align__(16) float As[8][128];
    __shared__ __align__(16) float Bs[8][128];

    int tid = threadIdx.x;
    int row0 = blockIdx.y * 128;
    int col0 = blockIdx.x * 128;
    int tx = tid & 15;     // 0..15
    int ty = tid >> 4;     // 0..15

    float acc[8][8];
#pragma unroll
    for (int i = 0; i < 8; i++)
#pragma unroll
        for (int j = 0; j < 8; j++) acc[i][j] = 0.f;

    int aRow = tid >> 1;          // 0..127
    int aCol = (tid & 1) * 4;     // 0 or 4
    int bRow = tid >> 5;          // 0..7
    int bCol = (tid & 31) * 4;    // 0..124

    bool aValid = (row0 + aRow) < M;
    const float* Aptr = A + (size_t)(row0 + aRow) * K + aCol;
    const float* Bptr = B + (size_t)bRow * Nn + col0 + bCol;

    for (int k0 = 0; k0 < K; k0 += 8) {
        float4 av = aValid ? *(const float4*)(Aptr + k0)
                           : make_float4(0.f, 0.f, 0.f, 0.f);
        As[aCol + 0][aRow] = av.x;
        As[aCol + 1][aRow] = av.y;
        As[aCol + 2][aRow] = av.z;
        As[aCol + 3][aRow] = av.w;
        *(float4*)&Bs[bRow][bCol] = *(const float4*)(Bptr + (size_t)k0 * Nn);
        __syncthreads();

#pragma unroll
        for (int k = 0; k < 8; k++) {
            float ar[8], br[8];
#pragma unroll
            for (int i = 0; i < 8; i++) ar[i] = As[k][ty * 8 + i];
#pragma unroll
            for (int j = 0; j < 8; j++) br[j] = Bs[k][tx * 8 + j];
#pragma unroll
            for (int i = 0; i < 8; i++)
#pragma unroll
                for (int j = 0; j < 8; j++)
                    acc[i][j] = fmaf(ar[i], br[j], acc[i][j]);
        }
        __syncthreads();
    }

#pragma unroll
    for (int i = 0; i < 8; i++) {
        int r = row0 + ty * 8 + i;
        if (r < M) {
            float4 v0 = make_float4(acc[i][0], acc[i][1], acc[i][2], acc[i][3]);
            float4 v1 = make_float4(acc[i][4], acc[i][5], acc[i][6], acc[i][7]);
            *(float4*)&C[(size_t)r * Nn + col0 + tx * 8]     = v0;
            *(float4*)&C[(size_t)r * Nn + col0 + tx * 8 + 4] = v1;
        }
    }
}

// ---------------- small-N GEMM: [M,512] x [512,16] ----------------
__global__ __launch_bounds__(256) void gemm_n16(
    int aSel, const float* __restrict__ W, int cSel, int M, int K)
{
    const float* A = pickbuf(aSel);
    float* C = pickbuf(cSel);
    __shared__ float Ws[512 * 16];
    int tid = threadIdx.x;
    for (int i = tid; i < K * 16; i += 256) Ws[i] = W[i];
    __syncthreads();
    int n = blockIdx.x * 16 + tid / 16;
    int c = tid % 16;
    if (n >= M) return;
    const float* a = A + (size_t)n * K;
    float acc = 0.f;
#pragma unroll 8
    for (int k = 0; k < K; k++) acc = fmaf(a[k], Ws[k * 16 + c], acc);
    C[(size_t)n * 16 + c] = acc;
}

// ---------------- attention coefficients: al_s/al_d per (node, head) ----------------
__global__ void attn_kernel(int hSel, const float* __restrict__ a_s,
                            const float* __restrict__ a_d, int H, int C)
{
    const float* h = pickbuf(hSel);
    int gw = (blockIdx.x * blockDim.x + threadIdx.x) >> 5;
    int lane = threadIdx.x & 31;
    if (gw >= NND * H) return;
    int n = gw / H, hh = gw - n * H;
    int HC = H * C;
    const float* hp = h + (size_t)n * HC + hh * C;
    float s = 0.f, d = 0.f;
    if (lane < C) {
        float v = hp[lane];
        s = v * a_s[hh * C + lane];
        d = v * a_d[hh * C + lane];
    }
    if (C > 32) {
        float v = hp[lane + 32];
        s = fmaf(v, a_s[hh * C + lane + 32], s);
        d = fmaf(v, a_d[hh * C + lane + 32], d);
    }
#pragma unroll
    for (int off = 16; off > 0; off >>= 1) {
        s += __shfl_down_sync(0xffffffffu, s, off);
        d += __shfl_down_sync(0xffffffffu, d, off);
    }
    if (lane == 0) { g_als[n * H + hh] = s; g_ald[n * H + hh] = d; }
}

// ---------------- softmax pass 1: max (init with self-loop, atomicMax over edges) ----
__global__ void init_node_kernel(int H) {
    int i = blockIdx.x * blockDim.x + threadIdx.x;
    if (i >= NND * H) return;
    g_menc[i] = fenc(lrelu(g_als[i] + g_ald[i]));  // self-loop e-value
}
__global__ void edge_max_kernel(int H) {
    int i = blockIdx.x * blockDim.x + threadIdx.x;
    if (i >= NED * H) return;
    int e = i / H, hh = i - e * H;
    int s = g_src[e], d = g_dst[e];
    float v = lrelu(g_als[s * H + hh] + g_ald[d * H + hh]);
    atomicMax(&g_menc[d * H + hh], fenc(v));
}
// ---------------- softmax pass 2: exp + denom ----------------
__global__ void init_denom_kernel(int H) {
    int i = blockIdx.x * blockDim.x + threadIdx.x;
    if (i >= NND * H) return;
    float m = fdec(g_menc[i]);
    g_mf[i] = m;
    float ex = expf(lrelu(g_als[i] + g_ald[i]) - m);
    g_exself[i] = ex;
    g_denom[i] = ex;
}
__global__ void edge_exp_kernel(int H) {
    int i = blockIdx.x * blockDim.x + threadIdx.x;
    if (i >= NED * H) return;
    int e = i / H, hh = i - e * H;
    int s = g_src[e], d = g_dst[e];
    float v = lrelu(g_als[s * H + hh] + g_ald[d * H + hh]);
    float ex = expf(v - g_mf[d * H + hh]);
    g_exbuf[i] = ex;
    atomicAdd(&g_denom[d * H + hh], ex);
}

// ---------------- softmax pass 3: CSR gather + bias + (optional) ELU -------------
template <int C>
__global__ void gather_kernel(int hSel, const float* __restrict__ bias,
                              float* __restrict__ Oext, int oSel,
                              int H, int do_elu)
{
    const float* h = pickbuf(hSel);
    float* out = (oSel < 0) ? Oext : pickbuf(oSel);
    int gw = (blockIdx.x * blockDim.x + threadIdx.x) >> 5;
    int lane = threadIdx.x & 31;
    if (gw >= NND * H) return;
    int n = gw / H, hh = gw - n * H;
    int HC = H * C;
    float inv = 1.0f / g_denom[n * H + hh];
    float a0 = g_exself[n * H + hh] * inv;
    const float* hp = h + (size_t)n * HC + hh * C;
    float acc0 = 0.f, acc1 = 0.f;
    if (lane < C) acc0 = a0 * hp[lane];
    if (C > 32) acc1 = a0 * hp[lane + 32];
    int beg = g_rowptr[n], end = g_rowptr[n + 1];
    for (int i = beg; i < end; i++) {
        int e = g_esort[i];
        float a = g_exbuf[e * H + hh] * inv;
        const float* hs = h + (size_t)g_src[e] * HC + hh * C;
        if (lane < C) acc0 = fmaf(a, hs[lane], acc0);
        if (C > 32) acc1 = fmaf(a, hs[lane + 32], acc1);
    }
    float* op = out + (size_t)n * HC + hh * C;
    if (lane < C) {
        float v = acc0 + bias[hh * C + lane];
        if (do_elu) v = v > 0.f ? v : expm1f(v);
        op[lane] = v;
    }
    if (C > 32) {
        float v = acc1 + bias[hh * C + lane + 32];
        if (do_elu) v = v > 0.f ? v : expm1f(v);
        op[lane + 32] = v;
    }
}

// ---------------- host launcher ----------------
static inline int cdiv(int a, int b) { return (a + b - 1) / b; }

static void run_attention(int hSel, const float* a_s, const float* a_d,
                          const float* bias, float* Oext, int oSel,
                          int H, int C, int do_elu)
{
    int nodeItems = NND * H;
    int edgeItems = NED * H;
    int warpBlocks = cdiv(nodeItems, 8);  // 8 warps / 256-thread block
    attn_kernel<<<warpBlocks, 256>>>(hSel, a_s, a_d, H, C);
    init_node_kernel<<<cdiv(nodeItems, 256), 256>>>(H);
    edge_max_kernel<<<cdiv(edgeItems, 256), 256>>>(H);
    init_denom_kernel<<<cdiv(nodeItems, 256), 256>>>(H);
    edge_exp_kernel<<<cdiv(edgeItems, 256), 256>>>(H);
    if (C == 64)
        gather_kernel<64><<<warpBlocks, 256>>>(hSel, bias, Oext, oSel, H, do_elu);
    else
        gather_kernel<16><<<warpBlocks, 256>>>(hSel, bias, Oext, oSel, H, do_elu);
}

extern "C" void kernel_launch(void* const* d_in, const int* in_sizes, int n_in,
                              void* d_out, int out_size)
{
    const float* x    = (const float*)d_in[0];
    const void*  ei   = d_in[1];
    const float* W0   = (const float*)d_in[2];
    const float* a_s0 = (const float*)d_in[3];
    const float* a_d0 = (const float*)d_in[4];
    const float* b0   = (const float*)d_in[5];
    const float* W1   = (const float*)d_in[6];
    const float* a_s1 = (const float*)d_in[7];
    const float* a_d1 = (const float*)d_in[8];
    const float* b1   = (const float*)d_in[9];
    const float* W2   = (const float*)d_in[10];
    const float* a_s2 = (const float*)d_in[11];
    const float* a_d2 = (const float*)d_in[12];
    const float* b2   = (const float*)d_in[13];
    float* out = (float*)d_out;

    // edge preprocessing + CSR build (recomputed every call; deterministic work)
    detect_kernel<<<1, 1>>>(ei);
    convert_kernel<<<cdiv(NED, 256), 256>>>(ei);
    zero_deg_kernel<<<cdiv(NND, 256), 256>>>();
    count_kernel<<<cdiv(NED, 256), 256>>>();
    scan_kernel<<<1, 1024>>>();
    scatter_kernel<<<cdiv(NED, 256), 256>>>();

    // ---- layer 0: x[50000,128] @ W0[128,512] -> bufA; attention -> bufB (ELU)
    {
        dim3 grid(512 / 128, cdiv(NND, 128));
        sgemm128<<<grid, 256>>>(x, -1, W0, /*cSel=*/0, NND, 128, 512);
    }
    run_attention(/*hSel=*/0, a_s0, a_d0, b0, nullptr, /*oSel=*/1, 8, 64, /*elu=*/1);

    // ---- layer 1: bufB @ W1[512,512] -> bufA; attention -> bufB (ELU)
    {
        dim3 grid(512 / 128, cdiv(NND, 128));
        sgemm128<<<grid, 256>>>(nullptr, /*aSel=*/1, W1, /*cSel=*/0, NND, 512, 512);
    }
    run_attention(/*hSel=*/0, a_s1, a_d1, b1, nullptr, /*oSel=*/1, 8, 64, /*elu=*/1);

    // ---- layer 2: bufB @ W2[512,16] -> bufC; attention (H=1,C=16) -> d_out
    gemm_n16<<<cdiv(NND, 16), 256>>>(/*aSel=*/1, W2, /*cSel=*/2, NND, 512);
    run_attention(/*hSel=*/2, a_s2, a_d2, b2, out, /*oSel=*/-1, 1, 16, /*elu=*/0);
}

// round 10
// speedup vs baseline: 1.1213x; 1.1213x over previous
#include <cuda_runtime.h>
#include <cstdint>

#define NND 50000
#define NED 400000

// ---------------- device scratch (no allocations allowed) ----------------
__device__ int g_is64;
__device__ int g_src[NED];
__device__ int g_dst[NED];
__device__ int g_deg[NND];
__device__ int g_rowptr[NND + 1];
__device__ int g_cursor[NND];
__device__ int g_esort[NED];

__device__ float g_bufA[(size_t)NND * 512];   // linear-transform output h
__device__ float g_bufB[(size_t)NND * 512];   // aggregated layer output
__device__ float g_bufC[(size_t)NND * 16];    // final-layer h

__device__ float g_als[NND * 8];
__device__ float g_ald[NND * 8];
__device__ unsigned int g_menc[NND * 8];
__device__ float g_mf[NND * 8];
__device__ float g_denom[NND * 8];
__device__ float g_exself[NND * 8];
__device__ float g_exbuf[(size_t)NED * 8];

__device__ __forceinline__ float* pickbuf(int s) {
    return s == 0 ? g_bufA : (s == 1 ? g_bufB : g_bufC);
}
// order-preserving float <-> uint encoding for atomicMax
__device__ __forceinline__ unsigned fenc(float f) {
    unsigned u = __float_as_uint(f);
    return (u & 0x80000000u) ? ~u : (u | 0x80000000u);
}
__device__ __forceinline__ float fdec(unsigned u) {
    return __uint_as_float((u & 0x80000000u) ? (u ^ 0x80000000u) : ~u);
}
__device__ __forceinline__ float lrelu(float v) { return v > 0.f ? v : 0.2f * v; }

// ---------------- edge index dtype detect + convert ----------------
__global__ void detect_kernel(const void* ei) {
    if (threadIdx.x == 0 && blockIdx.x == 0) {
        const int* p = (const int*)ei;
        int is64 = 1;
        for (int i = 0; i < 128; i++) {
            if (p[2 * i + 1] != 0) { is64 = 0; break; }
        }
        g_is64 = is64;
    }
}

__global__ void convert_kernel(const void* ei) {
    int e = blockIdx.x * blockDim.x + threadIdx.x;
    if (e >= NED) return;
    if (g_is64) {
        const long long* p = (const long long*)ei;
        g_src[e] = (int)p[e];
        g_dst[e] = (int)p[NED + e];
    } else {
        const int* p = (const int*)ei;
        g_src[e] = p[e];
        g_dst[e] = p[NED + e];
    }
}

// ---------------- CSR build (by destination) ----------------
__global__ void zero_deg_kernel() {
    int i = blockIdx.x * blockDim.x + threadIdx.x;
    if (i < NND) g_deg[i] = 0;
}
__global__ void count_kernel() {
    int e = blockIdx.x * blockDim.x + threadIdx.x;
    if (e >= NED) return;
    atomicAdd(&g_deg[g_dst[e]], 1);
}
__global__ void scan_kernel() {  // single block, 1024 threads
    __shared__ int sh[1024];
    __shared__ int s_carry;
    int tid = threadIdx.x;
    if (tid == 0) s_carry = 0;
    __syncthreads();
    for (int base = 0; base < NND; base += 1024) {
        int i = base + tid;
        int v = (i < NND) ? g_deg[i] : 0;
        sh[tid] = v;
        __syncthreads();
        for (int off = 1; off < 1024; off <<= 1) {
            int t = (tid >= off) ? sh[tid - off] : 0;
            __syncthreads();
            sh[tid] += t;
            __syncthreads();
        }
        int excl = s_carry + sh[tid] - v;
        if (i < NND) { g_rowptr[i] = excl; g_cursor[i] = excl; }
        __syncthreads();
        if (tid == 0) s_carry += sh[1023];
        __syncthreads();
    }
    if (tid == 0) g_rowptr[NND] = s_carry;
}
__global__ void scatter_kernel() {
    int e = blockIdx.x * blockDim.x + threadIdx.x;
    if (e >= NED) return;
    int pos = atomicAdd(&g_cursor[g_dst[e]], 1);
    g_esort[pos] = e;
}

// ---------------- tensor-core GEMM (3xTF32 mma.sync), 128x128x32 tiles ------------
// 4 warps, each computing a 64x64 warp tile via m16n8k8 fragments.
// Each operand split x = hi + lo (hi = tf32(x), lo = tf32(x - hi)); accumulate
// a_lo*b_hi + a_hi*b_lo + a_hi*b_hi  -> ~fp32 accuracy at 3x tensor-op count.
// Double-buffered smem filled with cp.async.cg (zero-fill on OOB rows).
#define TCBM 128
#define TCBN 128
#define TCBK 32
#define AS_STRIDE 36     // floats; conflict-free fragment LDS
#define BS_STRIDE 136
#define AS_TILE (TCBM * AS_STRIDE)
#define BS_TILE (TCBK * BS_STRIDE)
#define TC_SMEM_BYTES ((2 * AS_TILE + 2 * BS_TILE) * 4)   // 71680 B

__device__ __forceinline__ void cp16(uint32_t dst, const void* src, bool pred) {
    int sz = pred ? 16 : 0;
    asm volatile("cp.async.cg.shared.global [%0], [%1], 16, %2;\n"
                 :: "r"(dst), "l"(src), "r"(sz));
}
__device__ __forceinline__ void cp_commit() {
    asm volatile("cp.async.commit_group;\n" ::: "memory");
}
__device__ __forceinline__ uint32_t f2tf(float x) {
    uint32_t r;
    asm("cvt.rna.tf32.f32 %0, %1;\n" : "=r"(r) : "f"(x));
    return r;
}
__device__ __forceinline__ void mma_tf32(float* c, const uint32_t* a, const uint32_t* b) {
    asm volatile(
        "mma.sync.aligned.m16n8k8.row.col.f32.tf32.tf32.f32 "
        "{%0,%1,%2,%3}, {%4,%5,%6,%7}, {%8,%9}, {%0,%1,%2,%3};\n"
        : "+f"(c[0]), "+f"(c[1]), "+f"(c[2]), "+f"(c[3])
        : "r"(a[0]), "r"(a[1]), "r"(a[2]), "r"(a[3]), "r"(b[0]), "r"(b[1]));
}

__global__ __launch_bounds__(128) void sgemm_tc(
    const float* __restrict__ Aext, int aSel,
    const float* __restrict__ B, int cSel,
    int M, int K, int Nn)
{
    extern __shared__ float sm[];
    const float* A = (aSel < 0) ? Aext : pickbuf(aSel);
    float* C = pickbuf(cSel);

    float* AsBuf[2] = { sm, sm + AS_TILE };
    float* BsBuf[2] = { sm + 2 * AS_TILE, sm + 2 * AS_TILE + BS_TILE };
    uint32_t smBase = (uint32_t)__cvta_generic_to_shared(sm);
    uint32_t asAddr[2] = { smBase, smBase + AS_TILE * 4u };
    uint32_t bsAddr[2] = { smBase + 2u * AS_TILE * 4u,
                           smBase + (2u * AS_TILE + BS_TILE) * 4u };

    int tid = threadIdx.x;
    int warp = tid >> 5, lane = tid & 31;
    int g = lane >> 2, t = lane & 3;
    int row0 = blockIdx.y * TCBM;
    int col0 = blockIdx.x * TCBN;
    int mbase = (warp & 1) * 64;
    int nbase = (warp >> 1) * 64;

    float acc[4][8][4];
#pragma unroll
    for (int mf = 0; mf < 4; mf++)
#pragma unroll
        for (int nf = 0; nf < 8; nf++)
#pragma unroll
            for (int i = 0; i < 4; i++) acc[mf][nf][i] = 0.f;

    int T = K / TCBK;

    auto issue = [&](int tt, int bi) {
        int k0 = tt * TCBK;
#pragma unroll
        for (int i = 0; i < 8; i++) {
            int idx = tid + i * 128;
            int row = idx >> 3, kq = idx & 7;
            const float* src = A + (size_t)(row0 + row) * K + k0 + kq * 4;
            cp16(asAddr[bi] + (uint32_t)(row * AS_STRIDE + kq * 4) * 4u,
                 src, (row0 + row) < M);
        }
#pragma unroll
        for (int i = 0; i < 8; i++) {
            int idx = tid + i * 128;
            int nq = idx & 31, k = idx >> 5;
            const float* src = B + (size_t)(k0 + k) * Nn + col0 + nq * 4;
            cp16(bsAddr[bi] + (uint32_t)(k * BS_STRIDE + nq * 4) * 4u,
                 src, true);
        }
        cp_commit();
    };

    issue(0, 0);
    for (int tt = 0; tt < T; tt++) {
        int cur = tt & 1;
        if (tt + 1 < T) {
            issue(tt + 1, (tt + 1) & 1);
            asm volatile("cp.async.wait_group 1;\n" ::: "memory");
        } else {
            asm volatile("cp.async.wait_group 0;\n" ::: "memory");
        }
        __syncthreads();

        const float* as = AsBuf[cur];
        const float* bs = BsBuf[cur];
#pragma unroll
        for (int ks = 0; ks < 4; ks++) {
            uint32_t ahi[4][4], alo[4][4];
            uint32_t bhi[8][2], blo[8][2];
#pragma unroll
            for (int mf = 0; mf < 4; mf++) {
                const float* p = as + (mbase + mf * 16 + g) * AS_STRIDE + ks * 8 + t;
                const float* p2 = p + 8 * AS_STRIDE;
                float v0 = p[0], v1 = p2[0], v2 = p[4], v3 = p2[4];
                ahi[mf][0] = f2tf(v0); alo[mf][0] = f2tf(v0 - __uint_as_float(ahi[mf][0]));
                ahi[mf][1] = f2tf(v1); alo[mf][1] = f2tf(v1 - __uint_as_float(ahi[mf][1]));
                ahi[mf][2] = f2tf(v2); alo[mf][2] = f2tf(v2 - __uint_as_float(ahi[mf][2]));
                ahi[mf][3] = f2tf(v3); alo[mf][3] = f2tf(v3 - __uint_as_float(ahi[mf][3]));
            }
#pragma unroll
            for (int nf = 0; nf < 8; nf++) {
                const float* p = bs + (ks * 8 + t) * BS_STRIDE + nbase + nf * 8 + g;
                float v0 = p[0], v1 = p[4 * BS_STRIDE];
                bhi[nf][0] = f2tf(v0); blo[nf][0] = f2tf(v0 - __uint_as_float(bhi[nf][0]));
                bhi[nf][1] = f2tf(v1); blo[nf][1] = f2tf(v1 - __uint_as_float(bhi[nf][1]));
            }
#pragma unroll
            for (int mf = 0; mf < 4; mf++)
#pragma unroll
                for (int nf = 0; nf < 8; nf++) {
                    mma_tf32(acc[mf][nf], alo[mf], bhi[nf]);
                    mma_tf32(acc[mf][nf], ahi[mf], blo[nf]);
                    mma_tf32(acc[mf][nf], ahi[mf], bhi[nf]);
                }
        }
        __syncthreads();
    }

    // epilogue: c0/c1 at (row g, cols 2t,2t+1), c2/c3 at row g+8
#pragma unroll
    for (int mf = 0; mf < 4; mf++) {
        int r = row0 + mbase + mf * 16 + g;
#pragma unroll
        for (int nf = 0; nf < 8; nf++) {
            int c = col0 + nbase + nf * 8 + 2 * t;
            if (r < M)
                *(float2*)&C[(size_t)r * Nn + c] =
                    make_float2(acc[mf][nf][0], acc[mf][nf][1]);
            if (r + 8 < M)
                *(float2*)&C[(size_t)(r + 8) * Nn + c] =
                    make_float2(acc[mf][nf][2], acc[mf][nf][3]);
        }
    }
}

// ---------------- small-N GEMM: [M,512] x [512,16] ----------------
__global__ __launch_bounds__(256) void gemm_n16(
    int aSel, const float* __restrict__ W, int cSel, int M, int K)
{
    const float* A = pickbuf(aSel);
    float* C = pickbuf(cSel);
    __shared__ float Ws[512 * 16];
    int tid = threadIdx.x;
    for (int i = tid; i < K * 16; i += 256) Ws[i] = W[i];
    __syncthreads();
    int n = blockIdx.x * 16 + tid / 16;
    int c = tid % 16;
    if (n >= M) return;
    const float* a = A + (size_t)n * K;
    float acc = 0.f;
#pragma unroll 8
    for (int k = 0; k < K; k++) acc = fmaf(a[k], Ws[k * 16 + c], acc);
    C[(size_t)n * 16 + c] = acc;
}

// ---------------- attention coefficients: al_s/al_d per (node, head) ----------------
__global__ void attn_kernel(int hSel, const float* __restrict__ a_s,
                            const float* __restrict__ a_d, int H, int C)
{
    const float* h = pickbuf(hSel);
    int gw = (blockIdx.x * blockDim.x + threadIdx.x) >> 5;
    int lane = threadIdx.x & 31;
    if (gw >= NND * H) return;
    int n = gw / H, hh = gw - n * H;
    int HC = H * C;
    const float* hp = h + (size_t)n * HC + hh * C;
    float s = 0.f, d = 0.f;
    if (lane < C) {
        float v = hp[lane];
        s = v * a_s[hh * C + lane];
        d = v * a_d[hh * C + lane];
    }
    if (C > 32) {
        float v = hp[lane + 32];
        s = fmaf(v, a_s[hh * C + lane + 32], s);
        d = fmaf(v, a_d[hh * C + lane + 32], d);
    }
#pragma unroll
    for (int off = 16; off > 0; off >>= 1) {
        s += __shfl_down_sync(0xffffffffu, s, off);
        d += __shfl_down_sync(0xffffffffu, d, off);
    }
    if (lane == 0) { g_als[n * H + hh] = s; g_ald[n * H + hh] = d; }
}

// ---------------- softmax pass 1: max (init with self-loop, atomicMax over edges) ----
__global__ void init_node_kernel(int H) {
    int i = blockIdx.x * blockDim.x + threadIdx.x;
    if (i >= NND * H) return;
    g_menc[i] = fenc(lrelu(g_als[i] + g_ald[i]));  // self-loop e-value
}
__global__ void edge_max_kernel(int H) {
    int i = blockIdx.x * blockDim.x + threadIdx.x;
    if (i >= NED * H) return;
    int e = i / H, hh = i - e * H;
    int s = g_src[e], d = g_dst[e];
    float v = lrelu(g_als[s * H + hh] + g_ald[d * H + hh]);
    atomicMax(&g_menc[d * H + hh], fenc(v));
}
// ---------------- softmax pass 2: exp + denom ----------------
__global__ void init_denom_kernel(int H) {
    int i = blockIdx.x * blockDim.x + threadIdx.x;
    if (i >= NND * H) return;
    float m = fdec(g_menc[i]);
    g_mf[i] = m;
    float ex = expf(lrelu(g_als[i] + g_ald[i]) - m);
    g_exself[i] = ex;
    g_denom[i] = ex;
}
__global__ void edge_exp_kernel(int H) {
    int i = blockIdx.x * blockDim.x + threadIdx.x;
    if (i >= NED * H) return;
    int e = i / H, hh = i - e * H;
    int s = g_src[e], d = g_dst[e];
    float v = lrelu(g_als[s * H + hh] + g_ald[d * H + hh]);
    float ex = expf(v - g_mf[d * H + hh]);
    g_exbuf[i] = ex;
    atomicAdd(&g_denom[d * H + hh], ex);
}

// ---------------- softmax pass 3: CSR gather + bias + (optional) ELU -------------
template <int C>
__global__ void gather_kernel(int hSel, const float* __restrict__ bias,
                              float* __restrict__ Oext, int oSel,
                              int H, int do_elu)
{
    const float* h = pickbuf(hSel);
    float* out = (oSel < 0) ? Oext : pickbuf(oSel);
    int gw = (blockIdx.x * blockDim.x + threadIdx.x) >> 5;
    int lane = threadIdx.x & 31;
    if (gw >= NND * H) return;
    int n = gw / H, hh = gw - n * H;
    int HC = H * C;
    float inv = 1.0f / g_denom[n * H + hh];
    float a0 = g_exself[n * H + hh] * inv;
    const float* hp = h + (size_t)n * HC + hh * C;
    float acc0 = 0.f, acc1 = 0.f;
    if (lane < C) acc0 = a0 * hp[lane];
    if (C > 32) acc1 = a0 * hp[lane + 32];
    int beg = g_rowptr[n], end = g_rowptr[n + 1];
    for (int i = beg; i < end; i++) {
        int e = g_esort[i];
        float a = g_exbuf[e * H + hh] * inv;
        const float* hs = h + (size_t)g_src[e] * HC + hh * C;
        if (lane < C) acc0 = fmaf(a, hs[lane], acc0);
        if (C > 32) acc1 = fmaf(a, hs[lane + 32], acc1);
    }
    float* op = out + (size_t)n * HC + hh * C;
    if (lane < C) {
        float v = acc0 + bias[hh * C + lane];
        if (do_elu) v = v > 0.f ? v : expm1f(v);
        op[lane] = v;
    }
    if (C > 32) {
        float v = acc1 + bias[hh * C + lane + 32];
        if (do_elu) v = v > 0.f ? v : expm1f(v);
        op[lane + 32] = v;
    }
}

// ---------------- host launcher ----------------
static inline int cdiv(int a, int b) { return (a + b - 1) / b; }

static void run_attention(int hSel, const float* a_s, const float* a_d,
                          const float* bias, float* Oext, int oSel,
                          int H, int C, int do_elu)
{
    int nodeItems = NND * H;
    int edgeItems = NED * H;
    int warpBlocks = cdiv(nodeItems, 8);  // 8 warps / 256-thread block
    attn_kernel<<<warpBlocks, 256>>>(hSel, a_s, a_d, H, C);
    init_node_kernel<<<cdiv(nodeItems, 256), 256>>>(H);
    edge_max_kernel<<<cdiv(edgeItems, 256), 256>>>(H);
    init_denom_kernel<<<cdiv(nodeItems, 256), 256>>>(H);
    edge_exp_kernel<<<cdiv(edgeItems, 256), 256>>>(H);
    if (C == 64)
        gather_kernel<64><<<warpBlocks, 256>>>(hSel, bias, Oext, oSel, H, do_elu);
    else
        gather_kernel<16><<<warpBlocks, 256>>>(hSel, bias, Oext, oSel, H, do_elu);
}

extern "C" void kernel_launch(void* const* d_in, const int* in_sizes, int n_in,
                              void* d_out, int out_size)
{
    const float* x    = (const float*)d_in[0];
    const void*  ei   = d_in[1];
    const float* W0   = (const float*)d_in[2];
    const float* a_s0 = (const float*)d_in[3];
    const float* a_d0 = (const float*)d_in[4];
    const float* b0   = (const float*)d_in[5];
    const float* W1   = (const float*)d_in[6];
    const float* a_s1 = (const float*)d_in[7];
    const float* a_d1 = (const float*)d_in[8];
    const float* b1   = (const float*)d_in[9];
    const float* W2   = (const float*)d_in[10];
    const float* a_s2 = (const float*)d_in[11];
    const float* a_d2 = (const float*)d_in[12];
    const float* b2   = (const float*)d_in[13];
    float* out = (float*)d_out;

    // allow 70KB dynamic smem for the TC gemm (idempotent; host-side, not captured)
    cudaFuncSetAttribute(sgemm_tc, cudaFuncAttributeMaxDynamicSharedMemorySize,
                         TC_SMEM_BYTES);

    // edge preprocessing + CSR build (recomputed every call; deterministic work)
    detect_kernel<<<1, 1>>>(ei);
    convert_kernel<<<cdiv(NED, 256), 256>>>(ei);
    zero_deg_kernel<<<cdiv(NND, 256), 256>>>();
    count_kernel<<<cdiv(NED, 256), 256>>>();
    scan_kernel<<<1, 1024>>>();
    scatter_kernel<<<cdiv(NED, 256), 256>>>();

    // ---- layer 0: x[50000,128] @ W0[128,512] -> bufA; attention -> bufB (ELU)
    {
        dim3 grid(512 / TCBN, cdiv(NND, TCBM));
        sgemm_tc<<<grid, 128, TC_SMEM_BYTES>>>(x, -1, W0, /*cSel=*/0, NND, 128, 512);
    }
    run_attention(/*hSel=*/0, a_s0, a_d0, b0, nullptr, /*oSel=*/1, 8, 64, /*elu=*/1);

    // ---- layer 1: bufB @ W1[512,512] -> bufA; attention -> bufB (ELU)
    {
        dim3 grid(512 / TCBN, cdiv(NND, TCBM));
        sgemm_tc<<<grid, 128, TC_SMEM_BYTES>>>(nullptr, /*aSel=*/1, W1, /*cSel=*/0,
                                               NND, 512, 512);
    }
    run_attention(/*hSel=*/0, a_s1, a_d1, b1, nullptr, /*oSel=*/1, 8, 64, /*elu=*/1);

    // ---- layer 2: bufB @ W2[512,16] -> bufC; attention (H=1,C=16) -> d_out
    gemm_n16<<<cdiv(NND, 16), 256>>>(/*aSel=*/1, W2, /*cSel=*/2, NND, 512);
    run_attention(/*hSel=*/2, a_s2, a_d2, b2, out, /*oSel=*/-1, 1, 16, /*elu=*/0);
}

// round 13
// speedup vs baseline: 1.4268x; 1.2724x over previous
#include <cuda_runtime.h>
#include <cstdint>

#define NND 50000
#define NED 400000

// ---------------- device scratch (no allocations allowed) ----------------
__device__ int g_is64;
__device__ int g_src[NED];
__device__ int g_dst[NED];
__device__ int g_deg[NND];
__device__ int g_rowptr[NND + 1];
__device__ int g_cursor[NND];
__device__ int g_ssort[NED];      // src node id, sorted by dst (CSR order)
__device__ int g_bsum[64];

__device__ float g_bufA[(size_t)NND * 512];   // linear-transform output h
__device__ float g_bufB[(size_t)NND * 512];   // aggregated layer output
__device__ float g_bufC[(size_t)NND * 16];    // final-layer h

__device__ float g_als[NND * 8];
__device__ float g_ald[NND * 8];
__device__ float g_denom[NND * 8];
__device__ float g_exself[NND * 8];           // unnormalized self exp
__device__ float g_exbuf[(size_t)NED * 8];    // CSR-pos indexed: [pos*H + h]

__device__ __forceinline__ float* pickbuf(int s) {
    return s == 0 ? g_bufA : (s == 1 ? g_bufB : g_bufC);
}
__device__ __forceinline__ float lrelu(float v) { return v > 0.f ? v : 0.2f * v; }
__device__ __forceinline__ float4 fma4(float a, float4 v, float4 c) {
    c.x = fmaf(a, v.x, c.x); c.y = fmaf(a, v.y, c.y);
    c.z = fmaf(a, v.z, c.z); c.w = fmaf(a, v.w, c.w);
    return c;
}

// ---------------- edge index dtype detect + convert ----------------
__global__ void detect_kernel(const void* ei) {
    if (threadIdx.x == 0 && blockIdx.x == 0) {
        const int* p = (const int*)ei;
        int is64 = 1;
        for (int i = 0; i < 128; i++) {
            if (p[2 * i + 1] != 0) { is64 = 0; break; }
        }
        g_is64 = is64;
    }
}
__global__ void convert_kernel(const void* ei) {
    int e = blockIdx.x * blockDim.x + threadIdx.x;
    if (e >= NED) return;
    if (g_is64) {
        const long long* p = (const long long*)ei;
        g_src[e] = (int)p[e];
        g_dst[e] = (int)p[NED + e];
    } else {
        const int* p = (const int*)ei;
        g_src[e] = p[e];
        g_dst[e] = p[NED + e];
    }
}

// ---------------- CSR build (by destination) ----------------
__global__ void zero_deg_kernel() {
    int i = blockIdx.x * blockDim.x + threadIdx.x;
    if (i < NND) g_deg[i] = 0;
}
__global__ void count_kernel() {
    int e = blockIdx.x * blockDim.x + threadIdx.x;
    if (e >= NED) return;
    atomicAdd(&g_deg[g_dst[e]], 1);
}
// multi-block scan: per-block exclusive scan + block sums
__global__ void scanA_kernel() {
    __shared__ int sh[1024];
    int tid = threadIdx.x;
    int i = blockIdx.x * 1024 + tid;
    int v = (i < NND) ? g_deg[i] : 0;
    sh[tid] = v;
    __syncthreads();
    for (int off = 1; off < 1024; off <<= 1) {
        int t = (tid >= off) ? sh[tid - off] : 0;
        __syncthreads();
        sh[tid] += t;
        __syncthreads();
    }
    if (i < NND) g_rowptr[i] = sh[tid] - v;
    if (tid == 1023) g_bsum[blockIdx.x] = sh[1023];
}
__global__ void scanB_kernel(int nblk) {
    if (threadIdx.x == 0) {
        int run = 0;
        for (int b = 0; b < nblk; b++) {
            int t = g_bsum[b];
            g_bsum[b] = run;
            run += t;
        }
        g_rowptr[NND] = run;
    }
}
__global__ void scanC_kernel() {
    int i = blockIdx.x * blockDim.x + threadIdx.x;
    if (i >= NND) return;
    int v = g_rowptr[i] + g_bsum[i >> 10];
    g_rowptr[i] = v;
    g_cursor[i] = v;
}
__global__ void scatter_kernel() {
    int e = blockIdx.x * blockDim.x + threadIdx.x;
    if (e >= NED) return;
    int pos = atomicAdd(&g_cursor[g_dst[e]], 1);
    g_ssort[pos] = g_src[e];
}

// ---------------- tensor-core GEMM (3xTF32 mma.sync), 128x128x32 tiles ------------
#define TCBM 128
#define TCBN 128
#define TCBK 32
#define AS_STRIDE 36
#define BS_STRIDE 136
#define AS_TILE (TCBM * AS_STRIDE)
#define BS_TILE (TCBK * BS_STRIDE)
#define TC_SMEM_BYTES ((2 * AS_TILE + 2 * BS_TILE) * 4)   // 71680 B

__device__ __forceinline__ void cp16(uint32_t dst, const void* src, bool pred) {
    int sz = pred ? 16 : 0;
    asm volatile("cp.async.cg.shared.global [%0], [%1], 16, %2;\n"
                 :: "r"(dst), "l"(src), "r"(sz));
}
__device__ __forceinline__ void cp_commit() {
    asm volatile("cp.async.commit_group;\n" ::: "memory");
}
__device__ __forceinline__ uint32_t f2tf(float x) {
    uint32_t r;
    asm("cvt.rna.tf32.f32 %0, %1;\n" : "=r"(r) : "f"(x));
    return r;
}
__device__ __forceinline__ void mma_tf32(float* c, const uint32_t* a, const uint32_t* b) {
    asm volatile(
        "mma.sync.aligned.m16n8k8.row.col.f32.tf32.tf32.f32 "
        "{%0,%1,%2,%3}, {%4,%5,%6,%7}, {%8,%9}, {%0,%1,%2,%3};\n"
        : "+f"(c[0]), "+f"(c[1]), "+f"(c[2]), "+f"(c[3])
        : "r"(a[0]), "r"(a[1]), "r"(a[2]), "r"(a[3]), "r"(b[0]), "r"(b[1]));
}

__global__ __launch_bounds__(128) void sgemm_tc(
    const float* __restrict__ Aext, int aSel,
    const float* __restrict__ B, int cSel,
    int M, int K, int Nn)
{
    extern __shared__ float sm[];
    const float* A = (aSel < 0) ? Aext : pickbuf(aSel);
    float* C = pickbuf(cSel);

    float* AsBuf[2] = { sm, sm + AS_TILE };
    float* BsBuf[2] = { sm + 2 * AS_TILE, sm + 2 * AS_TILE + BS_TILE };
    uint32_t smBase = (uint32_t)__cvta_generic_to_shared(sm);
    uint32_t asAddr[2] = { smBase, smBase + AS_TILE * 4u };
    uint32_t bsAddr[2] = { smBase + 2u * AS_TILE * 4u,
                           smBase + (2u * AS_TILE + BS_TILE) * 4u };

    int tid = threadIdx.x;
    int warp = tid >> 5, lane = tid & 31;
    int g = lane >> 2, t = lane & 3;
    int row0 = blockIdx.y * TCBM;
    int col0 = blockIdx.x * TCBN;
    int mbase = (warp & 1) * 64;
    int nbase = (warp >> 1) * 64;

    float acc[4][8][4];
#pragma unroll
    for (int mf = 0; mf < 4; mf++)
#pragma unroll
        for (int nf = 0; nf < 8; nf++)
#pragma unroll
            for (int i = 0; i < 4; i++) acc[mf][nf][i] = 0.f;

    int T = K / TCBK;

    auto issue = [&](int tt, int bi) {
        int k0 = tt * TCBK;
#pragma unroll
        for (int i = 0; i < 8; i++) {
            int idx = tid + i * 128;
            int row = idx >> 3, kq = idx & 7;
            const float* src = A + (size_t)(row0 + row) * K + k0 + kq * 4;
            cp16(asAddr[bi] + (uint32_t)(row * AS_STRIDE + kq * 4) * 4u,
                 src, (row0 + row) < M);
        }
#pragma unroll
        for (int i = 0; i < 8; i++) {
            int idx = tid + i * 128;
            int nq = idx & 31, k = idx >> 5;
            const float* src = B + (size_t)(k0 + k) * Nn + col0 + nq * 4;
            cp16(bsAddr[bi] + (uint32_t)(k * BS_STRIDE + nq * 4) * 4u,
                 src, true);
        }
        cp_commit();
    };

    issue(0, 0);
    for (int tt = 0; tt < T; tt++) {
        int cur = tt & 1;
        if (tt + 1 < T) {
            issue(tt + 1, (tt + 1) & 1);
            asm volatile("cp.async.wait_group 1;\n" ::: "memory");
        } else {
            asm volatile("cp.async.wait_group 0;\n" ::: "memory");
        }
        __syncthreads();

        const float* as = AsBuf[cur];
        const float* bs = BsBuf[cur];
#pragma unroll
        for (int ks = 0; ks < 4; ks++) {
            uint32_t ahi[4][4], alo[4][4];
            uint32_t bhi[8][2], blo[8][2];
#pragma unroll
            for (int mf = 0; mf < 4; mf++) {
                const float* p = as + (mbase + mf * 16 + g) * AS_STRIDE + ks * 8 + t;
                const float* p2 = p + 8 * AS_STRIDE;
                float v0 = p[0], v1 = p2[0], v2 = p[4], v3 = p2[4];
                ahi[mf][0] = f2tf(v0); alo[mf][0] = f2tf(v0 - __uint_as_float(ahi[mf][0]));
                ahi[mf][1] = f2tf(v1); alo[mf][1] = f2tf(v1 - __uint_as_float(ahi[mf][1]));
                ahi[mf][2] = f2tf(v2); alo[mf][2] = f2tf(v2 - __uint_as_float(ahi[mf][2]));
                ahi[mf][3] = f2tf(v3); alo[mf][3] = f2tf(v3 - __uint_as_float(ahi[mf][3]));
            }
#pragma unroll
            for (int nf = 0; nf < 8; nf++) {
                const float* p = bs + (ks * 8 + t) * BS_STRIDE + nbase + nf * 8 + g;
                float v0 = p[0], v1 = p[4 * BS_STRIDE];
                bhi[nf][0] = f2tf(v0); blo[nf][0] = f2tf(v0 - __uint_as_float(bhi[nf][0]));
                bhi[nf][1] = f2tf(v1); blo[nf][1] = f2tf(v1 - __uint_as_float(bhi[nf][1]));
            }
#pragma unroll
            for (int mf = 0; mf < 4; mf++)
#pragma unroll
                for (int nf = 0; nf < 8; nf++) {
                    mma_tf32(acc[mf][nf], alo[mf], bhi[nf]);
                    mma_tf32(acc[mf][nf], ahi[mf], blo[nf]);
                    mma_tf32(acc[mf][nf], ahi[mf], bhi[nf]);
                }
        }
        __syncthreads();
    }

#pragma unroll
    for (int mf = 0; mf < 4; mf++) {
        int r = row0 + mbase + mf * 16 + g;
#pragma unroll
        for (int nf = 0; nf < 8; nf++) {
            int c = col0 + nbase + nf * 8 + 2 * t;
            if (r < M)
                *(float2*)&C[(size_t)r * Nn + c] =
                    make_float2(acc[mf][nf][0], acc[mf][nf][1]);
            if (r + 8 < M)
                *(float2*)&C[(size_t)(r + 8) * Nn + c] =
                    make_float2(acc[mf][nf][2], acc[mf][nf][3]);
        }
    }
}

// ---------------- small-N GEMM: [M,512] x [512,16] ----------------
__global__ __launch_bounds__(256) void gemm_n16(
    int aSel, const float* __restrict__ W, int cSel, int M, int K)
{
    const float* A = pickbuf(aSel);
    float* C = pickbuf(cSel);
    __shared__ float Ws[512 * 16];
    int tid = threadIdx.x;
    for (int i = tid; i < K * 16; i += 256) Ws[i] = W[i];
    __syncthreads();
    int n = blockIdx.x * 16 + tid / 16;
    int c = tid % 16;
    if (n >= M) return;
    const float* a = A + (size_t)n * K;
    float acc = 0.f;
#pragma unroll 8
    for (int k = 0; k < K; k++) acc = fmaf(a[k], Ws[k * 16 + c], acc);
    C[(size_t)n * 16 + c] = acc;
}

// ---------------- attention coefficients: al_s/al_d per (node, head) ----------------
__global__ void attn_kernel(int hSel, const float* __restrict__ a_s,
                            const float* __restrict__ a_d, int H, int C)
{
    const float* h = pickbuf(hSel);
    int gw = (blockIdx.x * blockDim.x + threadIdx.x) >> 5;
    int lane = threadIdx.x & 31;
    if (gw >= NND * H) return;
    int n = gw / H, hh = gw - n * H;
    int HC = H * C;
    const float* hp = h + (size_t)n * HC + hh * C;
    float s = 0.f, d = 0.f;
    if (lane < C) {
        float v = hp[lane];
        s = v * a_s[hh * C + lane];
        d = v * a_d[hh * C + lane];
    }
    if (C > 32) {
        float v = hp[lane + 32];
        s = fmaf(v, a_s[hh * C + lane + 32], s);
        d = fmaf(v, a_d[hh * C + lane + 32], d);
    }
#pragma unroll
    for (int off = 16; off > 0; off >>= 1) {
        s += __shfl_down_sync(0xffffffffu, s, off);
        d += __shfl_down_sync(0xffffffffu, d, off);
    }
    if (lane == 0) { g_als[n * H + hh] = s; g_ald[n * H + hh] = d; }
}

// ---------------- fused CSR softmax: warp per node, no atomics ----------------
// lanes organized as (32/H edge slots) x (H heads). Pass 1: compute logits ->
// g_exbuf (CSR order) + per-head max (shfl-reduce). Pass 2: exp + denom sum.
// Self-loop handled analytically (g_exself, g_denom).
template <int H>
__global__ __launch_bounds__(256) void softmax_csr() {
    int gw = (blockIdx.x * blockDim.x + threadIdx.x) >> 5;
    int lane = threadIdx.x & 31;
    if (gw >= NND) return;
    int n = gw;
    int hh = lane % H;
    int j = lane / H;
    const int JS = 32 / H;
    float ald = g_ald[n * H + hh];
    float eself = lrelu(g_als[n * H + hh] + ald);
    int beg = g_rowptr[n], end = g_rowptr[n + 1];

    float m = eself;
    for (int i = beg + j; i < end; i += JS) {
        int s = g_ssort[i];
        float e = lrelu(g_als[s * H + hh] + ald);
        g_exbuf[(size_t)i * H + hh] = e;
        m = fmaxf(m, e);
    }
#pragma unroll
    for (int off = H; off < 32; off <<= 1)
        m = fmaxf(m, __shfl_xor_sync(0xffffffffu, m, off));

    float sum = 0.f;
    for (int i = beg + j; i < end; i += JS) {
        float ex = expf(g_exbuf[(size_t)i * H + hh] - m);
        g_exbuf[(size_t)i * H + hh] = ex;
        sum += ex;
    }
    float exs = expf(eself - m);
    if (j == 0) sum += exs;
#pragma unroll
    for (int off = H; off < 32; off <<= 1)
        sum += __shfl_xor_sync(0xffffffffu, sum, off);
    if (j == 0) {
        g_denom[n * H + hh] = sum;
        g_exself[n * H + hh] = exs;
    }
}

// ---------------- gather, H=8 C=64: warp per node, all heads together ----------
// Lane covers channels 4*lane + 128*q (q=0..3) as float4; head(lane,q) =
// (lane>=16) + 2q is uniform per float4 -> alpha broadcast via shfl from lanes 0-7.
__global__ __launch_bounds__(256) void gather_h8(
    int hSel, const float* __restrict__ bias, int oSel)
{
    const float* h = pickbuf(hSel);
    float* out = pickbuf(oSel);
    int gw = (blockIdx.x * blockDim.x + threadIdx.x) >> 5;
    int lane = threadIdx.x & 31;
    if (gw >= NND) return;
    int n = gw;
    int hb = (lane >= 16) ? 1 : 0;

    float inv8 = 1.f, sa = 0.f;
    if (lane < 8) {
        inv8 = 1.0f / g_denom[n * 8 + lane];
        sa = g_exself[n * 8 + lane] * inv8;
    }

    float4 acc0, acc1, acc2, acc3;
    {
        const float4* hp = (const float4*)(h + (size_t)n * 512);
        float a0 = __shfl_sync(0xffffffffu, sa, hb);
        float a1 = __shfl_sync(0xffffffffu, sa, hb + 2);
        float a2 = __shfl_sync(0xffffffffu, sa, hb + 4);
        float a3 = __shfl_sync(0xffffffffu, sa, hb + 6);
        float4 z = make_float4(0.f, 0.f, 0.f, 0.f);
        acc0 = fma4(a0, hp[lane],      z);
        acc1 = fma4(a1, hp[lane + 32], z);
        acc2 = fma4(a2, hp[lane + 64], z);
        acc3 = fma4(a3, hp[lane + 96], z);
    }

    int beg = g_rowptr[n], end = g_rowptr[n + 1];
    for (int i = beg; i < end; i++) {
        int s = g_ssort[i];
        float av = 0.f;
        if (lane < 8) av = g_exbuf[(size_t)i * 8 + lane] * inv8;
        float a0 = __shfl_sync(0xffffffffu, av, hb);
        float a1 = __shfl_sync(0xffffffffu, av, hb + 2);
        float a2 = __shfl_sync(0xffffffffu, av, hb + 4);
        float a3 = __shfl_sync(0xffffffffu, av, hb + 6);
        const float4* hs = (const float4*)(h + (size_t)s * 512);
        acc0 = fma4(a0, hs[lane],      acc0);
        acc1 = fma4(a1, hs[lane + 32], acc1);
        acc2 = fma4(a2, hs[lane + 64], acc2);
        acc3 = fma4(a3, hs[lane + 96], acc3);
    }

    const float4* b4 = (const float4*)bias;
    float4* o4 = (float4*)(out + (size_t)n * 512);
    float4 bb, rr;
#define EMIT(ACC, OFF)                                                    \
    bb = b4[lane + OFF];                                                  \
    rr.x = ACC.x + bb.x; rr.y = ACC.y + bb.y;                             \
    rr.z = ACC.z + bb.z; rr.w = ACC.w + bb.w;                             \
    rr.x = rr.x > 0.f ? rr.x : expm1f(rr.x);                              \
    rr.y = rr.y > 0.f ? rr.y : expm1f(rr.y);                              \
    rr.z = rr.z > 0.f ? rr.z : expm1f(rr.z);                              \
    rr.w = rr.w > 0.f ? rr.w : expm1f(rr.w);                              \
    o4[lane + OFF] = rr;
    EMIT(acc0, 0)
    EMIT(acc1, 32)
    EMIT(acc2, 64)
    EMIT(acc3, 96)
#undef EMIT
}

// ---------------- gather, H=1 C=16: warp per node, final layer ----------------
__global__ __launch_bounds__(256) void gather_h1(
    int hSel, const float* __restrict__ bias, float* __restrict__ out)
{
    const float* h = pickbuf(hSel);
    int gw = (blockIdx.x * blockDim.x + threadIdx.x) >> 5;
    int lane = threadIdx.x & 31;
    if (gw >= NND) return;
    int n = gw;
    float inv = 1.0f / g_denom[n];
    float acc = 0.f;
    if (lane < 16) acc = g_exself[n] * inv * h[(size_t)n * 16 + lane];
    int beg = g_rowptr[n], end = g_rowptr[n + 1];
    for (int i = beg; i < end; i++) {
        int s = g_ssort[i];
        float a = g_exbuf[i] * inv;
        if (lane < 16) acc = fmaf(a, h[(size_t)s * 16 + lane], acc);
    }
    if (lane < 16) out[(size_t)n * 16 + lane] = acc + bias[lane];
}

// ---------------- host launcher ----------------
static inline int cdiv(int a, int b) { return (a + b - 1) / b; }

extern "C" void kernel_launch(void* const* d_in, const int* in_sizes, int n_in,
                              void* d_out, int out_size)
{
    const float* x    = (const float*)d_in[0];
    const void*  ei   = d_in[1];
    const float* W0   = (const float*)d_in[2];
    const float* a_s0 = (const float*)d_in[3];
    const float* a_d0 = (const float*)d_in[4];
    const float* b0   = (const float*)d_in[5];
    const float* W1   = (const float*)d_in[6];
    const float* a_s1 = (const float*)d_in[7];
    const float* a_d1 = (const float*)d_in[8];
    const float* b1   = (const float*)d_in[9];
    const float* W2   = (const float*)d_in[10];
    const float* a_s2 = (const float*)d_in[11];
    const float* a_d2 = (const float*)d_in[12];
    const float* b2   = (const float*)d_in[13];
    float* out = (float*)d_out;

    cudaFuncSetAttribute(sgemm_tc, cudaFuncAttributeMaxDynamicSharedMemorySize,
                         TC_SMEM_BYTES);

    int nodeBlocks = cdiv(NND, 8);          // warp-per-node kernels
    int scanBlocks = cdiv(NND, 1024);       // 49

    // --- CSR build interleaved so launch index 5 is sgemm_tc (ncu -s 5 -c 1) ---
    detect_kernel<<<1, 1>>>(ei);                                  // 0
    convert_kernel<<<cdiv(NED, 256), 256>>>(ei);                  // 1
    zero_deg_kernel<<<cdiv(NND, 256), 256>>>();                   // 2
    count_kernel<<<cdiv(NED, 256), 256>>>();                      // 3
    scanA_kernel<<<scanBlocks, 1024>>>();                         // 4
    // ---- layer 0 GEMM: x[50000,128] @ W0[128,512] -> bufA (independent of CSR)
    {
        dim3 grid(512 / TCBN, cdiv(NND, TCBM));
        sgemm_tc<<<grid, 128, TC_SMEM_BYTES>>>(x, -1, W0, 0, NND, 128, 512);  // 5
    }
    scanB_kernel<<<1, 32>>>(scanBlocks);                          // 6
    scanC_kernel<<<cdiv(NND, 256), 256>>>();                      // 7
    scatter_kernel<<<cdiv(NED, 256), 256>>>();                    // 8

    // ---- layer 0 attention -> bufB (ELU)
    attn_kernel<<<cdiv(NND * 8, 8), 256>>>(0, a_s0, a_d0, 8, 64);
    softmax_csr<8><<<nodeBlocks, 256>>>();
    gather_h8<<<nodeBlocks, 256>>>(0, b0, 1);

    // ---- layer 1: bufB @ W1[512,512] -> bufA; attention -> bufB (ELU)
    {
        dim3 grid(512 / TCBN, cdiv(NND, TCBM));
        sgemm_tc<<<grid, 128, TC_SMEM_BYTES>>>(nullptr, 1, W1, 0, NND, 512, 512);
    }
    attn_kernel<<<cdiv(NND * 8, 8), 256>>>(0, a_s1, a_d1, 8, 64);
    softmax_csr<8><<<nodeBlocks, 256>>>();
    gather_h8<<<nodeBlocks, 256>>>(0, b1, 1);

    // ---- layer 2: bufB @ W2[512,16] -> bufC; attention (H=1,C=16) -> d_out
    gemm_n16<<<cdiv(NND, 16), 256>>>(1, W2, 2, NND, 512);
    attn_kernel<<<cdiv(NND, 8), 256>>>(2, a_s2, a_d2, 1, 16);
    softmax_csr<1><<<nodeBlocks, 256>>>();
    gather_h1<<<nodeBlocks, 256>>>(2, b2, out);
}